// round 11
// baseline (speedup 1.0000x reference)
#include <cuda_runtime.h>
#include <cuda_fp16.h>
#include <mma.h>
#include <math.h>

#define NNODES 50000
#define NEDGES 800000
#define ETOT   (NEDGES + NNODES)
#define HC     128
#define NOUTC  40
#define NEG_SLOPE 0.2f
#define BN_EPS 1e-5f
#define NSCANB ((NNODES + 1023) / 1024)
#define FULLM 0xffffffffu

using namespace nvcuda;

// ---------------- scratch (static device arrays; no runtime alloc) ----------
static __device__ __align__(16) __half g_hh[NNODES * HC];   // h in fp16 (gather)
static __device__ __align__(16) float g_x1[NNODES * HC];
static __device__ __align__(16) float g_x2[NNODES * HC];
static __device__ float g_asrc[NNODES * 2];
static __device__ float g_adst[NNODES * 2];
static __device__ __align__(16) float g_e[ETOT * 2];   // ex per edge (CSR order)
static __device__ int   g_deg[NNODES];
static __device__ int   g_rowptr[NNODES + 1];
static __device__ int   g_bsum[NSCANB + 1];
static __device__ int   g_tick[ETOT];
static __device__ int   g_csr_src[ETOT];
static __device__ int   g_is64;

// ---------------- half2 <-> u32 bit casts ------------------------------------
__device__ __forceinline__ unsigned int h2_to_u32(__half2 h) {
    return *reinterpret_cast<unsigned int*>(&h);
}
__device__ __forceinline__ __half2 u32_to_h2(unsigned int u) {
    return *reinterpret_cast<__half2*>(&u);
}

// ---------------- init: zero degrees + edge dtype detect ---------------------
__global__ void k_init(const int* ei32) {
    int i = blockIdx.x * blockDim.x + threadIdx.x;
    if (i < NNODES) g_deg[i] = 0;
    if (i == 0) {
        int any = 0;
        #pragma unroll 1
        for (int k = 0; k < 256; k++) any |= ei32[2 * k + 1];
        g_is64 = (any == 0) ? 1 : 0;   // int64 ids < 50000 -> high words all 0
    }
}

__device__ __forceinline__ int edge_idx(const void* ei, int pos) {
    if (g_is64) return (int)((const long long*)ei)[pos];
    return ((const int*)ei)[pos];
}

// ---------------- CSR build --------------------------------------------------
__global__ void k_count(const void* ei) {
    int i = blockIdx.x * blockDim.x + threadIdx.x;
    if (i >= ETOT) return;
    int d = (i < NEDGES) ? edge_idx(ei, NEDGES + i) : (i - NEDGES);
    g_tick[i] = atomicAdd(&g_deg[d], 1);
}

__global__ void k_scan1() {
    __shared__ int s[1024];
    int t = threadIdx.x;
    int idx = blockIdx.x * 1024 + t;
    int v = (idx < NNODES) ? g_deg[idx] : 0;
    s[t] = v;
    __syncthreads();
    #pragma unroll
    for (int o = 1; o < 1024; o <<= 1) {
        int add = (t >= o) ? s[t - o] : 0;
        __syncthreads();
        s[t] += add;
        __syncthreads();
    }
    if (idx < NNODES) g_rowptr[idx + 1] = s[t];
    if (t == 1023) g_bsum[blockIdx.x] = s[1023];
    if (idx == 0) g_rowptr[0] = 0;
}

// merged block-sum prefix + offset add (warp-parallel prefix per block)
__global__ void k_scan3() {
    __shared__ int pre;
    int b = blockIdx.x;
    if (threadIdx.x < 32) {
        int v = 0;
        if (threadIdx.x < b) v = g_bsum[threadIdx.x];
        if (threadIdx.x + 32 < b) v += g_bsum[threadIdx.x + 32];
        #pragma unroll
        for (int o = 16; o; o >>= 1) v += __shfl_xor_sync(FULLM, v, o);
        if (threadIdx.x == 0) pre = v;
    }
    __syncthreads();
    int idx = b * 1024 + threadIdx.x;
    if (idx < NNODES) g_rowptr[idx + 1] += pre;
}

__global__ void k_fill(const void* ei) {
    int i = blockIdx.x * blockDim.x + threadIdx.x;
    if (i >= ETOT) return;
    int s, d;
    if (i < NEDGES) { s = edge_idx(ei, i); d = edge_idx(ei, NEDGES + i); }
    else            { s = d = i - NEDGES; }
    g_csr_src[g_rowptr[d] + g_tick[i]] = s;   // atomic-free (ticket)
}

// ------- tensor-core GEMM (wmma fp16, fp32 acc), fp16 C, fused attn dots -----
// block tile 64x128, K=128. 8 warps: warp w -> m-block (w>>1)*16, n-half (w&1)*64.
__global__ __launch_bounds__(256)
void k_gemm_tc(const float* __restrict__ A, const float* __restrict__ B,
               __half* __restrict__ C, int M,
               const float* __restrict__ att_src, const float* __restrict__ att_dst) {
    __shared__ __align__(16) __half As[64][16];
    __shared__ __align__(16) __half Bs[16][128];
    __shared__ __align__(16) float  Cs[64][128];
    int t = threadIdx.x;
    int rowBase = blockIdx.x * 64;
    int warp = t >> 5;
    int wm = warp >> 1;      // 0..3
    int wn = warp & 1;       // 0..1

    wmma::fragment<wmma::matrix_a, 16, 16, 16, __half, wmma::row_major> fa;
    wmma::fragment<wmma::matrix_b, 16, 16, 16, __half, wmma::row_major> fb;
    wmma::fragment<wmma::accumulator, 16, 16, 16, float> fc[4];
    #pragma unroll
    for (int j = 0; j < 4; j++) wmma::fill_fragment(fc[j], 0.0f);

    int aRow = t >> 2;           // 0..63
    int aC4  = (t & 3) * 4;      // 0,4,8,12
    int bRow = t >> 4;           // 0..15
    int bC8  = (t & 15) * 8;     // 0..120

    for (int k0 = 0; k0 < 128; k0 += 16) {
        // stage A 64x16 (fp32 -> fp16)
        float4 av = make_float4(0.f, 0.f, 0.f, 0.f);
        int gr = rowBase + aRow;
        if (gr < M)
            av = *reinterpret_cast<const float4*>(A + (size_t)gr * 128 + k0 + aC4);
        *reinterpret_cast<__half2*>(&As[aRow][aC4])     = __floats2half2_rn(av.x, av.y);
        *reinterpret_cast<__half2*>(&As[aRow][aC4 + 2]) = __floats2half2_rn(av.z, av.w);

        // stage B 16x128 (fp32 -> fp16)
        const float* bp = B + (size_t)(k0 + bRow) * 128 + bC8;
        float4 b0 = *reinterpret_cast<const float4*>(bp);
        float4 b1 = *reinterpret_cast<const float4*>(bp + 4);
        uint2 pb0, pb1;
        pb0.x = h2_to_u32(__floats2half2_rn(b0.x, b0.y));
        pb0.y = h2_to_u32(__floats2half2_rn(b0.z, b0.w));
        pb1.x = h2_to_u32(__floats2half2_rn(b1.x, b1.y));
        pb1.y = h2_to_u32(__floats2half2_rn(b1.z, b1.w));
        *reinterpret_cast<uint2*>(&Bs[bRow][bC8])     = pb0;
        *reinterpret_cast<uint2*>(&Bs[bRow][bC8 + 4]) = pb1;
        __syncthreads();

        wmma::load_matrix_sync(fa, &As[wm * 16][0], 16);
        #pragma unroll
        for (int j = 0; j < 4; j++) {
            wmma::load_matrix_sync(fb, &Bs[0][wn * 64 + j * 16], 128);
            wmma::mma_sync(fc[j], fa, fb, fc[j]);
        }
        __syncthreads();
    }

    // accumulators -> smem fp32
    #pragma unroll
    for (int j = 0; j < 4; j++)
        wmma::store_matrix_sync(&Cs[wm * 16][wn * 64 + j * 16], fc[j], 128,
                                wmma::mem_row_major);
    __syncthreads();

    // epilogue: fp16 C store + attention dots (4 threads per row, 32 cols each)
    {
        int r  = t >> 2;         // 0..63
        int cg = t & 3;          // col group: cg*32 .. cg*32+31
        int gr = rowBase + r;
        const float* crow = &Cs[r][cg * 32];
        float ss = 0.f, sd = 0.f;
        if (gr < M) {
            #pragma unroll
            for (int jj = 0; jj < 32; jj += 8) {
                float4 f0 = *reinterpret_cast<const float4*>(crow + jj);
                float4 f1 = *reinterpret_cast<const float4*>(crow + jj + 4);
                uint4 pk;
                pk.x = h2_to_u32(__floats2half2_rn(f0.x, f0.y));
                pk.y = h2_to_u32(__floats2half2_rn(f0.z, f0.w));
                pk.z = h2_to_u32(__floats2half2_rn(f1.x, f1.y));
                pk.w = h2_to_u32(__floats2half2_rn(f1.z, f1.w));
                *reinterpret_cast<uint4*>(C + (size_t)gr * 128 + cg * 32 + jj) = pk;
            }
        }
        #pragma unroll 8
        for (int jj = 0; jj < 32; jj++) {
            float c = crow[jj];
            ss += c * att_src[cg * 32 + jj];
            sd += c * att_dst[cg * 32 + jj];
        }
        // combine col-group pairs: (0,1)->head0, (2,3)->head1
        ss += __shfl_xor_sync(FULLM, ss, 1);
        sd += __shfl_xor_sync(FULLM, sd, 1);
        if (gr < M) {
            if (cg == 0) { g_asrc[gr * 2]     = ss; g_adst[gr * 2]     = sd; }
            if (cg == 2) { g_asrc[gr * 2 + 1] = ss; g_adst[gr * 2 + 1] = sd; }
        }
    }
}

// ------- fused softmax + aggregate: 2 passes, no max-shift, fast exp ---------
// softmax is shift-invariant; |e| <= ~10 here so exp(e) is safe in fp32.
template <bool FIRST>
__global__ __launch_bounds__(256)
void k_gat(const float* __restrict__ bias,
           const float* __restrict__ gamma, const float* __restrict__ beta,
           const float* __restrict__ mean,  const float* __restrict__ var) {
    int gt = blockIdx.x * blockDim.x + threadIdx.x;
    int w = gt >> 5, lane = gt & 31;
    if (w >= NNODES) return;
    int beg = g_rowptr[w], end = g_rowptr[w + 1];
    float ad0 = g_adst[w * 2], ad1 = g_adst[w * 2 + 1];

    // pass 1: ex = exp(leaky(e)), store; accumulate denominator (lane-strided)
    float s0 = 0.f, s1 = 0.f;
    for (int p = beg + lane; p < end; p += 32) {
        int s = g_csr_src[p];
        float2 av = *reinterpret_cast<const float2*>(g_asrc + 2 * s);
        float e0 = av.x + ad0;
        float e1 = av.y + ad1;
        e0 = e0 > 0.f ? e0 : NEG_SLOPE * e0;
        e1 = e1 > 0.f ? e1 : NEG_SLOPE * e1;
        float x0 = __expf(e0);
        float x1 = __expf(e1);
        float2 ev; ev.x = x0; ev.y = x1;
        *reinterpret_cast<float2*>(g_e + 2 * p) = ev;
        s0 += x0; s1 += x1;
    }
    #pragma unroll
    for (int o = 16; o; o >>= 1) {
        s0 += __shfl_xor_sync(FULLM, s0, o);
        s1 += __shfl_xor_sync(FULLM, s1, o);
    }
    float inv0 = 1.f / (s0 + 1e-16f);
    float inv1 = 1.f / (s1 + 1e-16f);
    float invh = (lane < 16) ? inv0 : inv1;
    __syncwarp();

    // pass 2: fp16 gather with broadcast ex * inv, dual accumulators for MLP
    float4 acc0 = make_float4(0.f, 0.f, 0.f, 0.f);
    float4 acc1 = make_float4(0.f, 0.f, 0.f, 0.f);
    int p = beg;
    for (; p + 1 < end; p += 2) {
        int s0i = g_csr_src[p];
        int s1i = g_csr_src[p + 1];
        float2 e0 = *reinterpret_cast<const float2*>(g_e + 2 * p);
        float2 e1 = *reinterpret_cast<const float2*>(g_e + 2 * (p + 1));
        float a0 = ((lane < 16) ? e0.x : e0.y) * invh;
        float a1 = ((lane < 16) ? e1.x : e1.y) * invh;
        uint2 u0 = *reinterpret_cast<const uint2*>(g_hh + (size_t)s0i * HC + lane * 4);
        uint2 u1 = *reinterpret_cast<const uint2*>(g_hh + (size_t)s1i * HC + lane * 4);
        float2 v0a = __half22float2(u32_to_h2(u0.x));
        float2 v0b = __half22float2(u32_to_h2(u0.y));
        float2 v1a = __half22float2(u32_to_h2(u1.x));
        float2 v1b = __half22float2(u32_to_h2(u1.y));
        acc0.x += a0 * v0a.x; acc0.y += a0 * v0a.y;
        acc0.z += a0 * v0b.x; acc0.w += a0 * v0b.y;
        acc1.x += a1 * v1a.x; acc1.y += a1 * v1a.y;
        acc1.z += a1 * v1b.x; acc1.w += a1 * v1b.y;
    }
    if (p < end) {
        int s0i = g_csr_src[p];
        float2 e0 = *reinterpret_cast<const float2*>(g_e + 2 * p);
        float a0 = ((lane < 16) ? e0.x : e0.y) * invh;
        uint2 u0 = *reinterpret_cast<const uint2*>(g_hh + (size_t)s0i * HC + lane * 4);
        float2 v0a = __half22float2(u32_to_h2(u0.x));
        float2 v0b = __half22float2(u32_to_h2(u0.y));
        acc0.x += a0 * v0a.x; acc0.y += a0 * v0a.y;
        acc0.z += a0 * v0b.x; acc0.w += a0 * v0b.y;
    }
    float4 acc = make_float4(acc0.x + acc1.x, acc0.y + acc1.y,
                             acc0.z + acc1.z, acc0.w + acc1.w);

    int j = lane * 4;
    float4 b = *reinterpret_cast<const float4*>(bias + j);
    float4 r = make_float4(acc.x + b.x, acc.y + b.y, acc.z + b.z, acc.w + b.w);
    if (FIRST) {
        float4 gm = *reinterpret_cast<const float4*>(gamma + j);
        float4 bt = *reinterpret_cast<const float4*>(beta + j);
        float4 mn = *reinterpret_cast<const float4*>(mean + j);
        float4 vr = *reinterpret_cast<const float4*>(var + j);
        r.x = (r.x - mn.x) * rsqrtf(vr.x + BN_EPS) * gm.x + bt.x;
        r.y = (r.y - mn.y) * rsqrtf(vr.y + BN_EPS) * gm.y + bt.y;
        r.z = (r.z - mn.z) * rsqrtf(vr.z + BN_EPS) * gm.z + bt.z;
        r.w = (r.w - mn.w) * rsqrtf(vr.w + BN_EPS) * gm.w + bt.w;
        r.x = r.x > 0.f ? r.x : expm1f(r.x);
        r.y = r.y > 0.f ? r.y : expm1f(r.y);
        r.z = r.z > 0.f ? r.z : expm1f(r.z);
        r.w = r.w > 0.f ? r.w : expm1f(r.w);
        *reinterpret_cast<float4*>(g_x1 + (size_t)w * HC + j) = r;
    } else {
        float4 p1 = *reinterpret_cast<const float4*>(g_x1 + (size_t)w * HC + j);
        r.x = fmaxf(r.x, p1.x); r.y = fmaxf(r.y, p1.y);
        r.z = fmaxf(r.z, p1.z); r.w = fmaxf(r.w, p1.w);        // JK 'max'
        *reinterpret_cast<float4*>(g_x2 + (size_t)w * HC + j) = r;
    }
}

// ------- head GEMM (M=64/block, Nc=40, K=128) + fused bias + log-softmax -----
__global__ __launch_bounds__(256)
void k_head(const float* __restrict__ A, const float* __restrict__ B,
            const float* __restrict__ bf, float* __restrict__ out, int M) {
    __shared__ __align__(16) float As[16][64];
    __shared__ __align__(16) float Bs[16][64];
    __shared__ float sred[64][17];
    __shared__ float srow[64];
    int t  = threadIdx.x;
    int tx = t & 15, ty = t >> 4;
    int rowBase = blockIdx.x * 64;

    float acc[4][4] = {};
    int aRow = t >> 2;
    int aK4  = (t & 3) * 4;
    int bK   = t >> 4;
    int bC4  = (t & 15) * 4;

    for (int k0 = 0; k0 < 128; k0 += 16) {
        float4 av = make_float4(0.f, 0.f, 0.f, 0.f);
        int gr = rowBase + aRow;
        if (gr < M) av = *reinterpret_cast<const float4*>(A + (size_t)gr * 128 + k0 + aK4);
        As[aK4 + 0][aRow] = av.x; As[aK4 + 1][aRow] = av.y;
        As[aK4 + 2][aRow] = av.z; As[aK4 + 3][aRow] = av.w;

        float4 bv = make_float4(0.f, 0.f, 0.f, 0.f);
        const float* brow = B + (size_t)(k0 + bK) * NOUTC;
        if (bC4 + 0 < NOUTC) bv.x = brow[bC4 + 0];
        if (bC4 + 1 < NOUTC) bv.y = brow[bC4 + 1];
        if (bC4 + 2 < NOUTC) bv.z = brow[bC4 + 2];
        if (bC4 + 3 < NOUTC) bv.w = brow[bC4 + 3];
        *reinterpret_cast<float4*>(&Bs[bK][bC4]) = bv;
        __syncthreads();

        #pragma unroll
        for (int k = 0; k < 16; k++) {
            float4 a4 = *reinterpret_cast<const float4*>(&As[k][ty * 4]);
            float4 b4 = *reinterpret_cast<const float4*>(&Bs[k][tx * 4]);
            float a[4] = {a4.x, a4.y, a4.z, a4.w};
            float b[4] = {b4.x, b4.y, b4.z, b4.w};
            #pragma unroll
            for (int i = 0; i < 4; i++)
                #pragma unroll
                for (int j = 0; j < 4; j++)
                    acc[i][j] += a[i] * b[j];
        }
        __syncthreads();
    }

    // add bias -> logits (cols tx*4+j, valid < 40)
    float bfv[4];
    #pragma unroll
    for (int j = 0; j < 4; j++)
        bfv[j] = (tx * 4 + j < NOUTC) ? bf[tx * 4 + j] : 0.f;
    #pragma unroll
    for (int i = 0; i < 4; i++)
        #pragma unroll
        for (int j = 0; j < 4; j++)
            acc[i][j] += bfv[j];

    // row max partials
    #pragma unroll
    for (int i = 0; i < 4; i++) {
        float pm = -3.0e38f;
        #pragma unroll
        for (int j = 0; j < 4; j++)
            if (tx * 4 + j < NOUTC) pm = fmaxf(pm, acc[i][j]);
        sred[ty * 4 + i][tx] = pm;
    }
    __syncthreads();
    if (t < 64) {
        float m = -3.0e38f;
        #pragma unroll
        for (int k = 0; k < 10; k++) m = fmaxf(m, sred[t][k]);
        srow[t] = m;
    }
    __syncthreads();
    // row sum partials
    #pragma unroll
    for (int i = 0; i < 4; i++) {
        float m = srow[ty * 4 + i];
        float ps = 0.f;
        #pragma unroll
        for (int j = 0; j < 4; j++)
            if (tx * 4 + j < NOUTC) ps += expf(acc[i][j] - m);
        sred[ty * 4 + i][tx] = ps;
    }
    __syncthreads();
    if (t < 64) {
        float s = 0.f;
        #pragma unroll
        for (int k = 0; k < 10; k++) s += sred[t][k];
        srow[t] += logf(s);           // lse
    }
    __syncthreads();

    #pragma unroll
    for (int i = 0; i < 4; i++) {
        int gr = rowBase + ty * 4 + i;
        if (gr >= M) continue;
        float lse = srow[ty * 4 + i];
        #pragma unroll
        for (int j = 0; j < 4; j++) {
            int gc = tx * 4 + j;
            if (gc < NOUTC) out[(size_t)gr * NOUTC + gc] = acc[i][j] - lse;
        }
    }
}

// ---------------- launch -----------------------------------------------------
extern "C" void kernel_launch(void* const* d_in, const int* in_sizes, int n_in,
                              void* d_out, int out_size) {
    const float* x     = (const float*)d_in[0];
    const void*  ei    = d_in[1];
    const float* W1    = (const float*)d_in[2];
    const float* as1   = (const float*)d_in[3];
    const float* ad1   = (const float*)d_in[4];
    const float* b1    = (const float*)d_in[5];
    const float* gamma = (const float*)d_in[6];
    const float* beta  = (const float*)d_in[7];
    const float* mean  = (const float*)d_in[8];
    const float* var   = (const float*)d_in[9];
    const float* W2    = (const float*)d_in[10];
    const float* as2   = (const float*)d_in[11];
    const float* ad2   = (const float*)d_in[12];
    const float* b2    = (const float*)d_in[13];
    const float* Wf    = (const float*)d_in[14];
    const float* bf    = (const float*)d_in[15];
    float* out = (float*)d_out;

    __half* hhP;
    float *x1P, *x2P;
    cudaGetSymbolAddress((void**)&hhP, g_hh);
    cudaGetSymbolAddress((void**)&x1P, g_x1);
    cudaGetSymbolAddress((void**)&x2P, g_x2);

    const int WPN = (NNODES * 32 + 255) / 256;   // warp-per-node grids

    k_init<<<(NNODES + 255) / 256, 256>>>((const int*)ei);
    k_count<<<(ETOT + 255) / 256, 256>>>(ei);
    k_scan1<<<NSCANB, 1024>>>();
    k_scan3<<<NSCANB, 1024>>>();
    k_fill<<<(ETOT + 255) / 256, 256>>>(ei);

    dim3 gemmG((NNODES + 63) / 64);

    // layer 1
    k_gemm_tc<<<gemmG, 256>>>(x, W1, hhP, NNODES, as1, ad1);
    k_gat<true><<<WPN, 256>>>(b1, gamma, beta, mean, var);

    // layer 2
    k_gemm_tc<<<gemmG, 256>>>(x1P, W2, hhP, NNODES, as2, ad2);
    k_gat<false><<<WPN, 256>>>(b2, nullptr, nullptr, nullptr, nullptr);

    // head: GEMM + bias + log-softmax fused
    k_head<<<(NNODES + 63) / 64, 256>>>(x2P, Wf, bf, out, NNODES);
}

// round 14
// speedup vs baseline: 1.0474x; 1.0474x over previous
#include <cuda_runtime.h>
#include <cuda_fp16.h>
#include <math.h>

#define NNODES 50000
#define NEDGES 800000
#define ETOT   (NEDGES + NNODES)
#define HC     128
#define NOUTC  40
#define NEG_SLOPE 0.2f
#define BN_EPS 1e-5f
#define NSCANB ((NNODES + 1023) / 1024)
#define FULLM 0xffffffffu

// ---------------- scratch (static device arrays; no runtime alloc) ----------
static __device__ __align__(16) __half g_hh[NNODES * HC];   // h in fp16 (gather)
static __device__ __align__(16) float g_x1[NNODES * HC];
static __device__ __align__(16) float g_x2[NNODES * HC];
static __device__ float g_asrc[NNODES * 2];
static __device__ float g_adst[NNODES * 2];
static __device__ __align__(16) float g_e[ETOT * 2];   // ex per edge (CSR order)
static __device__ int   g_deg[NNODES];
static __device__ int   g_rowptr[NNODES + 1];
static __device__ int   g_bsum[NSCANB + 1];
static __device__ int   g_tick[ETOT];
static __device__ int   g_csr_src[ETOT];
static __device__ int   g_is64;

// ---------------- half2 <-> u32 bit casts ------------------------------------
__device__ __forceinline__ unsigned int h2_to_u32(__half2 h) {
    return *reinterpret_cast<unsigned int*>(&h);
}
__device__ __forceinline__ __half2 u32_to_h2(unsigned int u) {
    return *reinterpret_cast<__half2*>(&u);
}

// ---------------- init: zero degrees + edge dtype detect ---------------------
__global__ void k_init(const int* ei32) {
    int i = blockIdx.x * blockDim.x + threadIdx.x;
    if (i < NNODES) g_deg[i] = 0;
    if (i == 0) {
        int any = 0;
        #pragma unroll 1
        for (int k = 0; k < 256; k++) any |= ei32[2 * k + 1];
        g_is64 = (any == 0) ? 1 : 0;   // int64 ids < 50000 -> high words all 0
    }
}

__device__ __forceinline__ int edge_idx(const void* ei, int pos) {
    if (g_is64) return (int)((const long long*)ei)[pos];
    return ((const int*)ei)[pos];
}

// ---------------- CSR build --------------------------------------------------
__global__ void k_count(const void* ei) {
    int i = blockIdx.x * blockDim.x + threadIdx.x;
    if (i >= ETOT) return;
    int d = (i < NEDGES) ? edge_idx(ei, NEDGES + i) : (i - NEDGES);
    g_tick[i] = atomicAdd(&g_deg[d], 1);
}

__global__ void k_scan1() {
    __shared__ int s[1024];
    int t = threadIdx.x;
    int idx = blockIdx.x * 1024 + t;
    int v = (idx < NNODES) ? g_deg[idx] : 0;
    s[t] = v;
    __syncthreads();
    #pragma unroll
    for (int o = 1; o < 1024; o <<= 1) {
        int add = (t >= o) ? s[t - o] : 0;
        __syncthreads();
        s[t] += add;
        __syncthreads();
    }
    if (idx < NNODES) g_rowptr[idx + 1] = s[t];
    if (t == 1023) g_bsum[blockIdx.x] = s[1023];
    if (idx == 0) g_rowptr[0] = 0;
}

// merged block-sum prefix + offset add (warp-parallel prefix per block)
__global__ void k_scan3() {
    __shared__ int pre;
    int b = blockIdx.x;
    if (threadIdx.x < 32) {
        int v = 0;
        if (threadIdx.x < b) v = g_bsum[threadIdx.x];
        if (threadIdx.x + 32 < b) v += g_bsum[threadIdx.x + 32];
        #pragma unroll
        for (int o = 16; o; o >>= 1) v += __shfl_xor_sync(FULLM, v, o);
        if (threadIdx.x == 0) pre = v;
    }
    __syncthreads();
    int idx = b * 1024 + threadIdx.x;
    if (idx < NNODES) g_rowptr[idx + 1] += pre;
}

__global__ void k_fill(const void* ei) {
    int i = blockIdx.x * blockDim.x + threadIdx.x;
    if (i >= ETOT) return;
    int s, d;
    if (i < NEDGES) { s = edge_idx(ei, i); d = edge_idx(ei, NEDGES + i); }
    else            { s = d = i - NEDGES; }
    g_csr_src[g_rowptr[d] + g_tick[i]] = s;   // atomic-free (ticket)
}

// ---------------- packed-f32x2 SGEMM (K=Nc=128), fp16 C, fused attn dots -----
__device__ __forceinline__ unsigned long long pack2(float a) {
    unsigned long long r;
    unsigned int u = __float_as_uint(a);
    asm("mov.b64 %0, {%1, %1};" : "=l"(r) : "r"(u));
    return r;
}
__device__ __forceinline__ float2 unpack2(unsigned long long v) {
    float2 f;
    asm("mov.b64 {%0, %1}, %2;" : "=f"(f.x), "=f"(f.y) : "l"(v));
    return f;
}

__global__ __launch_bounds__(256, 2)
void k_sgemm128(const float* __restrict__ A, const float* __restrict__ B,
                __half* __restrict__ C, int M,
                const float* __restrict__ att_src, const float* __restrict__ att_dst) {
    __shared__ __align__(16) float As[16][128];   // transposed A tile
    __shared__ __align__(16) float Bs[16][128];
    int t  = threadIdx.x;
    int tx = t & 15, ty = t >> 4;
    int rowBase = blockIdx.x * 128;

    unsigned long long acc[8][4];
    #pragma unroll
    for (int i = 0; i < 8; i++)
        #pragma unroll
        for (int j = 0; j < 4; j++) acc[i][j] = 0ull;

    int aRow = t >> 1;          // 0..127
    int aK   = (t & 1) * 8;     // 0 or 8
    int bRow = t >> 4;          // 0..15
    int bC   = (t & 15) * 8;    // 0..120

    for (int k0 = 0; k0 < 128; k0 += 16) {
        float4 av0 = make_float4(0.f, 0.f, 0.f, 0.f), av1 = av0;
        int gr = rowBase + aRow;
        if (gr < M) {
            const float* ap = A + (size_t)gr * 128 + k0 + aK;
            av0 = *reinterpret_cast<const float4*>(ap);
            av1 = *reinterpret_cast<const float4*>(ap + 4);
        }
        As[aK + 0][aRow] = av0.x; As[aK + 1][aRow] = av0.y;
        As[aK + 2][aRow] = av0.z; As[aK + 3][aRow] = av0.w;
        As[aK + 4][aRow] = av1.x; As[aK + 5][aRow] = av1.y;
        As[aK + 6][aRow] = av1.z; As[aK + 7][aRow] = av1.w;

        const float* bp = B + (size_t)(k0 + bRow) * 128 + bC;
        *reinterpret_cast<float4*>(&Bs[bRow][bC])     = *reinterpret_cast<const float4*>(bp);
        *reinterpret_cast<float4*>(&Bs[bRow][bC + 4]) = *reinterpret_cast<const float4*>(bp + 4);
        __syncthreads();

        #pragma unroll
        for (int k = 0; k < 16; k++) {
            float4 a0 = *reinterpret_cast<const float4*>(&As[k][ty * 8]);
            float4 a1 = *reinterpret_cast<const float4*>(&As[k][ty * 8 + 4]);
            unsigned long long aa[8];
            aa[0] = pack2(a0.x); aa[1] = pack2(a0.y); aa[2] = pack2(a0.z); aa[3] = pack2(a0.w);
            aa[4] = pack2(a1.x); aa[5] = pack2(a1.y); aa[6] = pack2(a1.z); aa[7] = pack2(a1.w);
            const unsigned long long* bpp =
                reinterpret_cast<const unsigned long long*>(&Bs[k][tx * 8]);
            unsigned long long b0 = bpp[0], b1 = bpp[1], b2 = bpp[2], b3 = bpp[3];
            #pragma unroll
            for (int i = 0; i < 8; i++) {
                asm("fma.rn.f32x2 %0, %1, %2, %0;" : "+l"(acc[i][0]) : "l"(aa[i]), "l"(b0));
                asm("fma.rn.f32x2 %0, %1, %2, %0;" : "+l"(acc[i][1]) : "l"(aa[i]), "l"(b1));
                asm("fma.rn.f32x2 %0, %1, %2, %0;" : "+l"(acc[i][2]) : "l"(aa[i]), "l"(b2));
                asm("fma.rn.f32x2 %0, %1, %2, %0;" : "+l"(acc[i][3]) : "l"(aa[i]), "l"(b3));
            }
        }
        __syncthreads();
    }

    // store C as fp16 (8 cols = 4 half2 = 16 B per thread-row)
    #pragma unroll
    for (int i = 0; i < 8; i++) {
        int gr = rowBase + ty * 8 + i;
        if (gr >= M) continue;
        uint4 pk;
        float2 c0 = unpack2(acc[i][0]);
        float2 c1 = unpack2(acc[i][1]);
        float2 c2 = unpack2(acc[i][2]);
        float2 c3 = unpack2(acc[i][3]);
        pk.x = h2_to_u32(__float22half2_rn(c0));
        pk.y = h2_to_u32(__float22half2_rn(c1));
        pk.z = h2_to_u32(__float22half2_rn(c2));
        pk.w = h2_to_u32(__float22half2_rn(c3));
        *reinterpret_cast<uint4*>(C + (size_t)gr * 128 + tx * 8) = pk;
    }

    // fused attention dot-products (fp32 accumulators)
    float asv[8], adv[8];
    #pragma unroll
    for (int j = 0; j < 8; j++) {
        asv[j] = att_src[tx * 8 + j];
        adv[j] = att_dst[tx * 8 + j];
    }
    float* sredS = &As[0][0];   // [128][16]
    float* sredD = &Bs[0][0];
    #pragma unroll
    for (int i = 0; i < 8; i++) {
        float ps = 0.f, pd = 0.f;
        #pragma unroll
        for (int j = 0; j < 4; j++) {
            float2 c = unpack2(acc[i][j]);
            ps += c.x * asv[2 * j] + c.y * asv[2 * j + 1];
            pd += c.x * adv[2 * j] + c.y * adv[2 * j + 1];
        }
        int row = ty * 8 + i;
        sredS[row * 16 + tx] = ps;
        sredD[row * 16 + tx] = pd;
    }
    __syncthreads();
    {
        int row  = t >> 1;
        int half = t & 1;
        int gr = rowBase + row;
        if (gr < M) {
            float ss = 0.f, sd = 0.f;
            #pragma unroll
            for (int k = 0; k < 8; k++) {
                ss += sredS[row * 16 + half * 8 + k];
                sd += sredD[row * 16 + half * 8 + k];
            }
            g_asrc[gr * 2 + half] = ss;
            g_adst[gr * 2 + half] = sd;
        }
    }
}

// ------- fused softmax + aggregate: 2 passes, no max-shift, fast exp ---------
// softmax is shift-invariant; |e| <= ~10 here so exp(e) is safe in fp32.
template <bool FIRST>
__global__ __launch_bounds__(256)
void k_gat(const float* __restrict__ bias,
           const float* __restrict__ gamma, const float* __restrict__ beta,
           const float* __restrict__ mean,  const float* __restrict__ var) {
    int gt = blockIdx.x * blockDim.x + threadIdx.x;
    int w = gt >> 5, lane = gt & 31;
    if (w >= NNODES) return;
    int beg = g_rowptr[w], end = g_rowptr[w + 1];
    float ad0 = g_adst[w * 2], ad1 = g_adst[w * 2 + 1];

    // pass 1: ex = exp(leaky(e)), store; accumulate denominator (lane-strided)
    float s0 = 0.f, s1 = 0.f;
    for (int p = beg + lane; p < end; p += 32) {
        int s = g_csr_src[p];
        float2 av = *reinterpret_cast<const float2*>(g_asrc + 2 * s);
        float e0 = av.x + ad0;
        float e1 = av.y + ad1;
        e0 = e0 > 0.f ? e0 : NEG_SLOPE * e0;
        e1 = e1 > 0.f ? e1 : NEG_SLOPE * e1;
        float x0 = __expf(e0);
        float x1 = __expf(e1);
        float2 ev; ev.x = x0; ev.y = x1;
        *reinterpret_cast<float2*>(g_e + 2 * p) = ev;
        s0 += x0; s1 += x1;
    }
    #pragma unroll
    for (int o = 16; o; o >>= 1) {
        s0 += __shfl_xor_sync(FULLM, s0, o);
        s1 += __shfl_xor_sync(FULLM, s1, o);
    }
    float inv0 = 1.f / (s0 + 1e-16f);
    float inv1 = 1.f / (s1 + 1e-16f);
    float invh = (lane < 16) ? inv0 : inv1;
    __syncwarp();

    // pass 2: fp16 gather with broadcast ex * inv, QUAD accumulators for MLP
    float4 ac0 = make_float4(0.f, 0.f, 0.f, 0.f);
    float4 ac1 = make_float4(0.f, 0.f, 0.f, 0.f);
    float4 ac2 = make_float4(0.f, 0.f, 0.f, 0.f);
    float4 ac3 = make_float4(0.f, 0.f, 0.f, 0.f);
    int p = beg;
    for (; p + 3 < end; p += 4) {
        int i0 = g_csr_src[p];
        int i1 = g_csr_src[p + 1];
        int i2 = g_csr_src[p + 2];
        int i3 = g_csr_src[p + 3];
        float2 e0 = *reinterpret_cast<const float2*>(g_e + 2 * p);
        float2 e1 = *reinterpret_cast<const float2*>(g_e + 2 * (p + 1));
        float2 e2 = *reinterpret_cast<const float2*>(g_e + 2 * (p + 2));
        float2 e3 = *reinterpret_cast<const float2*>(g_e + 2 * (p + 3));
        uint2 u0 = *reinterpret_cast<const uint2*>(g_hh + (size_t)i0 * HC + lane * 4);
        uint2 u1 = *reinterpret_cast<const uint2*>(g_hh + (size_t)i1 * HC + lane * 4);
        uint2 u2 = *reinterpret_cast<const uint2*>(g_hh + (size_t)i2 * HC + lane * 4);
        uint2 u3 = *reinterpret_cast<const uint2*>(g_hh + (size_t)i3 * HC + lane * 4);
        float a0 = ((lane < 16) ? e0.x : e0.y) * invh;
        float a1 = ((lane < 16) ? e1.x : e1.y) * invh;
        float a2 = ((lane < 16) ? e2.x : e2.y) * invh;
        float a3 = ((lane < 16) ? e3.x : e3.y) * invh;
        float2 va, vb;
        va = __half22float2(u32_to_h2(u0.x)); vb = __half22float2(u32_to_h2(u0.y));
        ac0.x += a0 * va.x; ac0.y += a0 * va.y; ac0.z += a0 * vb.x; ac0.w += a0 * vb.y;
        va = __half22float2(u32_to_h2(u1.x)); vb = __half22float2(u32_to_h2(u1.y));
        ac1.x += a1 * va.x; ac1.y += a1 * va.y; ac1.z += a1 * vb.x; ac1.w += a1 * vb.y;
        va = __half22float2(u32_to_h2(u2.x)); vb = __half22float2(u32_to_h2(u2.y));
        ac2.x += a2 * va.x; ac2.y += a2 * va.y; ac2.z += a2 * vb.x; ac2.w += a2 * vb.y;
        va = __half22float2(u32_to_h2(u3.x)); vb = __half22float2(u32_to_h2(u3.y));
        ac3.x += a3 * va.x; ac3.y += a3 * va.y; ac3.z += a3 * vb.x; ac3.w += a3 * vb.y;
    }
    for (; p < end; p++) {
        int i0 = g_csr_src[p];
        float2 e0 = *reinterpret_cast<const float2*>(g_e + 2 * p);
        float a0 = ((lane < 16) ? e0.x : e0.y) * invh;
        uint2 u0 = *reinterpret_cast<const uint2*>(g_hh + (size_t)i0 * HC + lane * 4);
        float2 va = __half22float2(u32_to_h2(u0.x));
        float2 vb = __half22float2(u32_to_h2(u0.y));
        ac0.x += a0 * va.x; ac0.y += a0 * va.y;
        ac0.z += a0 * vb.x; ac0.w += a0 * vb.y;
    }
    float4 acc = make_float4(ac0.x + ac1.x + ac2.x + ac3.x,
                             ac0.y + ac1.y + ac2.y + ac3.y,
                             ac0.z + ac1.z + ac2.z + ac3.z,
                             ac0.w + ac1.w + ac2.w + ac3.w);

    int j = lane * 4;
    float4 b = *reinterpret_cast<const float4*>(bias + j);
    float4 r = make_float4(acc.x + b.x, acc.y + b.y, acc.z + b.z, acc.w + b.w);
    if (FIRST) {
        float4 gm = *reinterpret_cast<const float4*>(gamma + j);
        float4 bt = *reinterpret_cast<const float4*>(beta + j);
        float4 mn = *reinterpret_cast<const float4*>(mean + j);
        float4 vr = *reinterpret_cast<const float4*>(var + j);
        r.x = (r.x - mn.x) * rsqrtf(vr.x + BN_EPS) * gm.x + bt.x;
        r.y = (r.y - mn.y) * rsqrtf(vr.y + BN_EPS) * gm.y + bt.y;
        r.z = (r.z - mn.z) * rsqrtf(vr.z + BN_EPS) * gm.z + bt.z;
        r.w = (r.w - mn.w) * rsqrtf(vr.w + BN_EPS) * gm.w + bt.w;
        r.x = r.x > 0.f ? r.x : expm1f(r.x);
        r.y = r.y > 0.f ? r.y : expm1f(r.y);
        r.z = r.z > 0.f ? r.z : expm1f(r.z);
        r.w = r.w > 0.f ? r.w : expm1f(r.w);
        *reinterpret_cast<float4*>(g_x1 + (size_t)w * HC + j) = r;
    } else {
        float4 p1 = *reinterpret_cast<const float4*>(g_x1 + (size_t)w * HC + j);
        r.x = fmaxf(r.x, p1.x); r.y = fmaxf(r.y, p1.y);
        r.z = fmaxf(r.z, p1.z); r.w = fmaxf(r.w, p1.w);        // JK 'max'
        *reinterpret_cast<float4*>(g_x2 + (size_t)w * HC + j) = r;
    }
}

// ------- head GEMM (M=64/block, Nc=40, K=128) + fused bias + log-softmax -----
__global__ __launch_bounds__(256)
void k_head(const float* __restrict__ A, const float* __restrict__ B,
            const float* __restrict__ bf, float* __restrict__ out, int M) {
    __shared__ __align__(16) float As[16][64];
    __shared__ __align__(16) float Bs[16][64];
    __shared__ float sred[64][17];
    __shared__ float srow[64];
    int t  = threadIdx.x;
    int tx = t & 15, ty = t >> 4;
    int rowBase = blockIdx.x * 64;

    float acc[4][4] = {};
    int aRow = t >> 2;
    int aK4  = (t & 3) * 4;
    int bK   = t >> 4;
    int bC4  = (t & 15) * 4;

    for (int k0 = 0; k0 < 128; k0 += 16) {
        float4 av = make_float4(0.f, 0.f, 0.f, 0.f);
        int gr = rowBase + aRow;
        if (gr < M) av = *reinterpret_cast<const float4*>(A + (size_t)gr * 128 + k0 + aK4);
        As[aK4 + 0][aRow] = av.x; As[aK4 + 1][aRow] = av.y;
        As[aK4 + 2][aRow] = av.z; As[aK4 + 3][aRow] = av.w;

        float4 bv = make_float4(0.f, 0.f, 0.f, 0.f);
        const float* brow = B + (size_t)(k0 + bK) * NOUTC;
        if (bC4 + 0 < NOUTC) bv.x = brow[bC4 + 0];
        if (bC4 + 1 < NOUTC) bv.y = brow[bC4 + 1];
        if (bC4 + 2 < NOUTC) bv.z = brow[bC4 + 2];
        if (bC4 + 3 < NOUTC) bv.w = brow[bC4 + 3];
        *reinterpret_cast<float4*>(&Bs[bK][bC4]) = bv;
        __syncthreads();

        #pragma unroll
        for (int k = 0; k < 16; k++) {
            float4 a4 = *reinterpret_cast<const float4*>(&As[k][ty * 4]);
            float4 b4 = *reinterpret_cast<const float4*>(&Bs[k][tx * 4]);
            float a[4] = {a4.x, a4.y, a4.z, a4.w};
            float b[4] = {b4.x, b4.y, b4.z, b4.w};
            #pragma unroll
            for (int i = 0; i < 4; i++)
                #pragma unroll
                for (int j = 0; j < 4; j++)
                    acc[i][j] += a[i] * b[j];
        }
        __syncthreads();
    }

    // add bias -> logits (cols tx*4+j, valid < 40)
    float bfv[4];
    #pragma unroll
    for (int j = 0; j < 4; j++)
        bfv[j] = (tx * 4 + j < NOUTC) ? bf[tx * 4 + j] : 0.f;
    #pragma unroll
    for (int i = 0; i < 4; i++)
        #pragma unroll
        for (int j = 0; j < 4; j++)
            acc[i][j] += bfv[j];

    // row max partials
    #pragma unroll
    for (int i = 0; i < 4; i++) {
        float pm = -3.0e38f;
        #pragma unroll
        for (int j = 0; j < 4; j++)
            if (tx * 4 + j < NOUTC) pm = fmaxf(pm, acc[i][j]);
        sred[ty * 4 + i][tx] = pm;
    }
    __syncthreads();
    if (t < 64) {
        float m = -3.0e38f;
        #pragma unroll
        for (int k = 0; k < 10; k++) m = fmaxf(m, sred[t][k]);
        srow[t] = m;
    }
    __syncthreads();
    // row sum partials
    #pragma unroll
    for (int i = 0; i < 4; i++) {
        float m = srow[ty * 4 + i];
        float ps = 0.f;
        #pragma unroll
        for (int j = 0; j < 4; j++)
            if (tx * 4 + j < NOUTC) ps += expf(acc[i][j] - m);
        sred[ty * 4 + i][tx] = ps;
    }
    __syncthreads();
    if (t < 64) {
        float s = 0.f;
        #pragma unroll
        for (int k = 0; k < 10; k++) s += sred[t][k];
        srow[t] += logf(s);           // lse
    }
    __syncthreads();

    #pragma unroll
    for (int i = 0; i < 4; i++) {
        int gr = rowBase + ty * 4 + i;
        if (gr >= M) continue;
        float lse = srow[ty * 4 + i];
        #pragma unroll
        for (int j = 0; j < 4; j++) {
            int gc = tx * 4 + j;
            if (gc < NOUTC) out[(size_t)gr * NOUTC + gc] = acc[i][j] - lse;
        }
    }
}

// ---------------- launch (single stream — no fork) ---------------------------
extern "C" void kernel_launch(void* const* d_in, const int* in_sizes, int n_in,
                              void* d_out, int out_size) {
    const float* x     = (const float*)d_in[0];
    const void*  ei    = d_in[1];
    const float* W1    = (const float*)d_in[2];
    const float* as1   = (const float*)d_in[3];
    const float* ad1   = (const float*)d_in[4];
    const float* b1    = (const float*)d_in[5];
    const float* gamma = (const float*)d_in[6];
    const float* beta  = (const float*)d_in[7];
    const float* mean  = (const float*)d_in[8];
    const float* var   = (const float*)d_in[9];
    const float* W2    = (const float*)d_in[10];
    const float* as2   = (const float*)d_in[11];
    const float* ad2   = (const float*)d_in[12];
    const float* b2    = (const float*)d_in[13];
    const float* Wf    = (const float*)d_in[14];
    const float* bf    = (const float*)d_in[15];
    float* out = (float*)d_out;

    __half* hhP;
    float *x1P, *x2P;
    cudaGetSymbolAddress((void**)&hhP, g_hh);
    cudaGetSymbolAddress((void**)&x1P, g_x1);
    cudaGetSymbolAddress((void**)&x2P, g_x2);

    const int WPN = (NNODES * 32 + 255) / 256;   // warp-per-node grids
    dim3 gemmG((NNODES + 127) / 128);

    k_init<<<(NNODES + 255) / 256, 256>>>((const int*)ei);
    k_count<<<(ETOT + 255) / 256, 256>>>(ei);
    k_scan1<<<NSCANB, 1024>>>();
    k_scan3<<<NSCANB, 1024>>>();
    k_fill<<<(ETOT + 255) / 256, 256>>>(ei);

    // layer 1
    k_sgemm128<<<gemmG, 256>>>(x, W1, hhP, NNODES, as1, ad1);
    k_gat<true><<<WPN, 256>>>(b1, gamma, beta, mean, var);

    // layer 2
    k_sgemm128<<<gemmG, 256>>>(x1P, W2, hhP, NNODES, as2, ad2);
    k_gat<false><<<WPN, 256>>>(b2, nullptr, nullptr, nullptr, nullptr);

    // head: GEMM + bias + log-softmax fused
    k_head<<<(NNODES + 63) / 64, 256>>>(x2P, Wf, bf, out, NNODES);
}

// round 16
// speedup vs baseline: 1.1187x; 1.0681x over previous
#include <cuda_runtime.h>
#include <cuda_fp16.h>
#include <math.h>

#define NNODES 50000
#define NEDGES 800000
#define ETOT   (NEDGES + NNODES)
#define HC     128
#define NOUTC  40
#define NEG_SLOPE 0.2f
#define BN_EPS 1e-5f
#define NSCANB ((NNODES + 1023) / 1024)
#define FULLM 0xffffffffu
#define DEGCAP 64

// ---------------- scratch (static device arrays; no runtime alloc) ----------
static __device__ __align__(16) __half g_hh[NNODES * HC];   // h in fp16 (gather)
static __device__ __align__(16) float g_x1[NNODES * HC];
static __device__ __align__(16) float g_x2[NNODES * HC];
static __device__ float g_asrc[NNODES * 2];
static __device__ float g_adst[NNODES * 2];
static __device__ __align__(16) float g_e[ETOT * 2];   // ex per edge (fallback only)
static __device__ int   g_deg[NNODES];
static __device__ int   g_rowptr[NNODES + 1];
static __device__ int   g_bsum[NSCANB + 1];
static __device__ int   g_tick[ETOT];
static __device__ int   g_csr_src[ETOT];
static __device__ int   g_is64;

// ---------------- half2 <-> u32 bit casts ------------------------------------
__device__ __forceinline__ unsigned int h2_to_u32(__half2 h) {
    return *reinterpret_cast<unsigned int*>(&h);
}
__device__ __forceinline__ __half2 u32_to_h2(unsigned int u) {
    return *reinterpret_cast<__half2*>(&u);
}

// ---------------- init: zero degrees + edge dtype detect ---------------------
__global__ void k_init(const int* ei32) {
    int i = blockIdx.x * blockDim.x + threadIdx.x;
    if (i < NNODES) g_deg[i] = 0;
    if (i == 0) {
        int any = 0;
        #pragma unroll 1
        for (int k = 0; k < 256; k++) any |= ei32[2 * k + 1];
        g_is64 = (any == 0) ? 1 : 0;   // int64 ids < 50000 -> high words all 0
    }
}

__device__ __forceinline__ int edge_idx(const void* ei, int pos) {
    if (g_is64) return (int)((const long long*)ei)[pos];
    return ((const int*)ei)[pos];
}

// ---------------- CSR build --------------------------------------------------
__global__ void k_count(const void* ei) {
    int i = blockIdx.x * blockDim.x + threadIdx.x;
    if (i >= ETOT) return;
    int d = (i < NEDGES) ? edge_idx(ei, NEDGES + i) : (i - NEDGES);
    g_tick[i] = atomicAdd(&g_deg[d], 1);
}

__global__ void k_scan1() {
    __shared__ int s[1024];
    int t = threadIdx.x;
    int idx = blockIdx.x * 1024 + t;
    int v = (idx < NNODES) ? g_deg[idx] : 0;
    s[t] = v;
    __syncthreads();
    #pragma unroll
    for (int o = 1; o < 1024; o <<= 1) {
        int add = (t >= o) ? s[t - o] : 0;
        __syncthreads();
        s[t] += add;
        __syncthreads();
    }
    if (idx < NNODES) g_rowptr[idx + 1] = s[t];
    if (t == 1023) g_bsum[blockIdx.x] = s[1023];
    if (idx == 0) g_rowptr[0] = 0;
}

// merged block-sum prefix + offset add (warp-parallel prefix per block)
__global__ void k_scan3() {
    __shared__ int pre;
    int b = blockIdx.x;
    if (threadIdx.x < 32) {
        int v = 0;
        if (threadIdx.x < b) v = g_bsum[threadIdx.x];
        if (threadIdx.x + 32 < b) v += g_bsum[threadIdx.x + 32];
        #pragma unroll
        for (int o = 16; o; o >>= 1) v += __shfl_xor_sync(FULLM, v, o);
        if (threadIdx.x == 0) pre = v;
    }
    __syncthreads();
    int idx = b * 1024 + threadIdx.x;
    if (idx < NNODES) g_rowptr[idx + 1] += pre;
}

__global__ void k_fill(const void* ei) {
    int i = blockIdx.x * blockDim.x + threadIdx.x;
    if (i >= ETOT) return;
    int s, d;
    if (i < NEDGES) { s = edge_idx(ei, i); d = edge_idx(ei, NEDGES + i); }
    else            { s = d = i - NEDGES; }
    g_csr_src[g_rowptr[d] + g_tick[i]] = s;   // atomic-free (ticket)
}

// ---------------- packed-f32x2 SGEMM (K=Nc=128), fp16 C, fused attn dots -----
__device__ __forceinline__ unsigned long long pack2(float a) {
    unsigned long long r;
    unsigned int u = __float_as_uint(a);
    asm("mov.b64 %0, {%1, %1};" : "=l"(r) : "r"(u));
    return r;
}
__device__ __forceinline__ float2 unpack2(unsigned long long v) {
    float2 f;
    asm("mov.b64 {%0, %1}, %2;" : "=f"(f.x), "=f"(f.y) : "l"(v));
    return f;
}

__global__ __launch_bounds__(256, 2)
void k_sgemm128(const float* __restrict__ A, const float* __restrict__ B,
                __half* __restrict__ C, int M,
                const float* __restrict__ att_src, const float* __restrict__ att_dst) {
    __shared__ __align__(16) float As[16][128];   // transposed A tile
    __shared__ __align__(16) float Bs[16][128];
    int t  = threadIdx.x;
    int tx = t & 15, ty = t >> 4;
    int rowBase = blockIdx.x * 128;

    unsigned long long acc[8][4];
    #pragma unroll
    for (int i = 0; i < 8; i++)
        #pragma unroll
        for (int j = 0; j < 4; j++) acc[i][j] = 0ull;

    int aRow = t >> 1;          // 0..127
    int aK   = (t & 1) * 8;     // 0 or 8
    int bRow = t >> 4;          // 0..15
    int bC   = (t & 15) * 8;    // 0..120

    for (int k0 = 0; k0 < 128; k0 += 16) {
        float4 av0 = make_float4(0.f, 0.f, 0.f, 0.f), av1 = av0;
        int gr = rowBase + aRow;
        if (gr < M) {
            const float* ap = A + (size_t)gr * 128 + k0 + aK;
            av0 = *reinterpret_cast<const float4*>(ap);
            av1 = *reinterpret_cast<const float4*>(ap + 4);
        }
        As[aK + 0][aRow] = av0.x; As[aK + 1][aRow] = av0.y;
        As[aK + 2][aRow] = av0.z; As[aK + 3][aRow] = av0.w;
        As[aK + 4][aRow] = av1.x; As[aK + 5][aRow] = av1.y;
        As[aK + 6][aRow] = av1.z; As[aK + 7][aRow] = av1.w;

        const float* bp = B + (size_t)(k0 + bRow) * 128 + bC;
        *reinterpret_cast<float4*>(&Bs[bRow][bC])     = *reinterpret_cast<const float4*>(bp);
        *reinterpret_cast<float4*>(&Bs[bRow][bC + 4]) = *reinterpret_cast<const float4*>(bp + 4);
        __syncthreads();

        #pragma unroll
        for (int k = 0; k < 16; k++) {
            float4 a0 = *reinterpret_cast<const float4*>(&As[k][ty * 8]);
            float4 a1 = *reinterpret_cast<const float4*>(&As[k][ty * 8 + 4]);
            unsigned long long aa[8];
            aa[0] = pack2(a0.x); aa[1] = pack2(a0.y); aa[2] = pack2(a0.z); aa[3] = pack2(a0.w);
            aa[4] = pack2(a1.x); aa[5] = pack2(a1.y); aa[6] = pack2(a1.z); aa[7] = pack2(a1.w);
            const unsigned long long* bpp =
                reinterpret_cast<const unsigned long long*>(&Bs[k][tx * 8]);
            unsigned long long b0 = bpp[0], b1 = bpp[1], b2 = bpp[2], b3 = bpp[3];
            #pragma unroll
            for (int i = 0; i < 8; i++) {
                asm("fma.rn.f32x2 %0, %1, %2, %0;" : "+l"(acc[i][0]) : "l"(aa[i]), "l"(b0));
                asm("fma.rn.f32x2 %0, %1, %2, %0;" : "+l"(acc[i][1]) : "l"(aa[i]), "l"(b1));
                asm("fma.rn.f32x2 %0, %1, %2, %0;" : "+l"(acc[i][2]) : "l"(aa[i]), "l"(b2));
                asm("fma.rn.f32x2 %0, %1, %2, %0;" : "+l"(acc[i][3]) : "l"(aa[i]), "l"(b3));
            }
        }
        __syncthreads();
    }

    // store C as fp16 (8 cols = 4 half2 = 16 B per thread-row)
    #pragma unroll
    for (int i = 0; i < 8; i++) {
        int gr = rowBase + ty * 8 + i;
        if (gr >= M) continue;
        uint4 pk;
        float2 c0 = unpack2(acc[i][0]);
        float2 c1 = unpack2(acc[i][1]);
        float2 c2 = unpack2(acc[i][2]);
        float2 c3 = unpack2(acc[i][3]);
        pk.x = h2_to_u32(__float22half2_rn(c0));
        pk.y = h2_to_u32(__float22half2_rn(c1));
        pk.z = h2_to_u32(__float22half2_rn(c2));
        pk.w = h2_to_u32(__float22half2_rn(c3));
        *reinterpret_cast<uint4*>(C + (size_t)gr * 128 + tx * 8) = pk;
    }

    // fused attention dot-products (fp32 accumulators)
    float asv[8], adv[8];
    #pragma unroll
    for (int j = 0; j < 8; j++) {
        asv[j] = att_src[tx * 8 + j];
        adv[j] = att_dst[tx * 8 + j];
    }
    float* sredS = &As[0][0];   // [128][16]
    float* sredD = &Bs[0][0];
    #pragma unroll
    for (int i = 0; i < 8; i++) {
        float ps = 0.f, pd = 0.f;
        #pragma unroll
        for (int j = 0; j < 4; j++) {
            float2 c = unpack2(acc[i][j]);
            ps += c.x * asv[2 * j] + c.y * asv[2 * j + 1];
            pd += c.x * adv[2 * j] + c.y * adv[2 * j + 1];
        }
        int row = ty * 8 + i;
        sredS[row * 16 + tx] = ps;
        sredD[row * 16 + tx] = pd;
    }
    __syncthreads();
    {
        int row  = t >> 1;
        int half = t & 1;
        int gr = rowBase + row;
        if (gr < M) {
            float ss = 0.f, sd = 0.f;
            #pragma unroll
            for (int k = 0; k < 8; k++) {
                ss += sredS[row * 16 + half * 8 + k];
                sd += sredD[row * 16 + half * 8 + k];
            }
            g_asrc[gr * 2 + half] = ss;
            g_adst[gr * 2 + half] = sd;
        }
    }
}

// ------- fused softmax + aggregate: smem-staged (src, ex), dual-unroll gather -
// softmax is shift-invariant; |e| <= ~10 here so exp(e) is safe in fp32.
template <bool FIRST>
__global__ __launch_bounds__(256)
void k_gat(const float* __restrict__ bias,
           const float* __restrict__ gamma, const float* __restrict__ beta,
           const float* __restrict__ mean,  const float* __restrict__ var) {
    __shared__ float2 s_ex[8][DEGCAP];
    __shared__ int    s_src[8][DEGCAP];
    int gt = blockIdx.x * blockDim.x + threadIdx.x;
    int w = gt >> 5, lane = gt & 31;
    if (w >= NNODES) return;
    int wl = (threadIdx.x >> 5);
    int beg = g_rowptr[w], end = g_rowptr[w + 1];
    int deg = end - beg;
    bool fits = (deg <= DEGCAP);
    float ad0 = g_adst[w * 2], ad1 = g_adst[w * 2 + 1];

    // pass 1: ex = exp(leaky(e)); stage (src, ex) in smem (fallback: global)
    float s0 = 0.f, s1 = 0.f;
    for (int p = beg + lane; p < end; p += 32) {
        int s = g_csr_src[p];
        float2 av = *reinterpret_cast<const float2*>(g_asrc + 2 * s);
        float e0 = av.x + ad0;
        float e1 = av.y + ad1;
        e0 = e0 > 0.f ? e0 : NEG_SLOPE * e0;
        e1 = e1 > 0.f ? e1 : NEG_SLOPE * e1;
        float x0 = __expf(e0);
        float x1 = __expf(e1);
        float2 ev; ev.x = x0; ev.y = x1;
        if (fits) {
            s_ex[wl][p - beg] = ev;
            s_src[wl][p - beg] = s;
        } else {
            *reinterpret_cast<float2*>(g_e + 2 * p) = ev;
        }
        s0 += x0; s1 += x1;
    }
    #pragma unroll
    for (int o = 16; o; o >>= 1) {
        s0 += __shfl_xor_sync(FULLM, s0, o);
        s1 += __shfl_xor_sync(FULLM, s1, o);
    }
    float inv0 = 1.f / (s0 + 1e-16f);
    float inv1 = 1.f / (s1 + 1e-16f);
    float invh = (lane < 16) ? inv0 : inv1;
    __syncwarp();

    // pass 2: fp16 gather with broadcast ex * inv, dual accumulators
    float4 acc0 = make_float4(0.f, 0.f, 0.f, 0.f);
    float4 acc1 = make_float4(0.f, 0.f, 0.f, 0.f);
    if (fits) {
        int k = 0;
        for (; k + 1 < deg; k += 2) {
            int s0i = s_src[wl][k];
            int s1i = s_src[wl][k + 1];
            float2 e0 = s_ex[wl][k];
            float2 e1 = s_ex[wl][k + 1];
            float a0 = ((lane < 16) ? e0.x : e0.y) * invh;
            float a1 = ((lane < 16) ? e1.x : e1.y) * invh;
            uint2 u0 = *reinterpret_cast<const uint2*>(g_hh + (size_t)s0i * HC + lane * 4);
            uint2 u1 = *reinterpret_cast<const uint2*>(g_hh + (size_t)s1i * HC + lane * 4);
            float2 v0a = __half22float2(u32_to_h2(u0.x));
            float2 v0b = __half22float2(u32_to_h2(u0.y));
            float2 v1a = __half22float2(u32_to_h2(u1.x));
            float2 v1b = __half22float2(u32_to_h2(u1.y));
            acc0.x += a0 * v0a.x; acc0.y += a0 * v0a.y;
            acc0.z += a0 * v0b.x; acc0.w += a0 * v0b.y;
            acc1.x += a1 * v1a.x; acc1.y += a1 * v1a.y;
            acc1.z += a1 * v1b.x; acc1.w += a1 * v1b.y;
        }
        if (k < deg) {
            int s0i = s_src[wl][k];
            float2 e0 = s_ex[wl][k];
            float a0 = ((lane < 16) ? e0.x : e0.y) * invh;
            uint2 u0 = *reinterpret_cast<const uint2*>(g_hh + (size_t)s0i * HC + lane * 4);
            float2 v0a = __half22float2(u32_to_h2(u0.x));
            float2 v0b = __half22float2(u32_to_h2(u0.y));
            acc0.x += a0 * v0a.x; acc0.y += a0 * v0a.y;
            acc0.z += a0 * v0b.x; acc0.w += a0 * v0b.y;
        }
    } else {
        int p = beg;
        for (; p + 1 < end; p += 2) {
            int s0i = g_csr_src[p];
            int s1i = g_csr_src[p + 1];
            float2 e0 = *reinterpret_cast<const float2*>(g_e + 2 * p);
            float2 e1 = *reinterpret_cast<const float2*>(g_e + 2 * (p + 1));
            float a0 = ((lane < 16) ? e0.x : e0.y) * invh;
            float a1 = ((lane < 16) ? e1.x : e1.y) * invh;
            uint2 u0 = *reinterpret_cast<const uint2*>(g_hh + (size_t)s0i * HC + lane * 4);
            uint2 u1 = *reinterpret_cast<const uint2*>(g_hh + (size_t)s1i * HC + lane * 4);
            float2 v0a = __half22float2(u32_to_h2(u0.x));
            float2 v0b = __half22float2(u32_to_h2(u0.y));
            float2 v1a = __half22float2(u32_to_h2(u1.x));
            float2 v1b = __half22float2(u32_to_h2(u1.y));
            acc0.x += a0 * v0a.x; acc0.y += a0 * v0a.y;
            acc0.z += a0 * v0b.x; acc0.w += a0 * v0b.y;
            acc1.x += a1 * v1a.x; acc1.y += a1 * v1a.y;
            acc1.z += a1 * v1b.x; acc1.w += a1 * v1b.y;
        }
        if (p < end) {
            int s0i = g_csr_src[p];
            float2 e0 = *reinterpret_cast<const float2*>(g_e + 2 * p);
            float a0 = ((lane < 16) ? e0.x : e0.y) * invh;
            uint2 u0 = *reinterpret_cast<const uint2*>(g_hh + (size_t)s0i * HC + lane * 4);
            float2 v0a = __half22float2(u32_to_h2(u0.x));
            float2 v0b = __half22float2(u32_to_h2(u0.y));
            acc0.x += a0 * v0a.x; acc0.y += a0 * v0a.y;
            acc0.z += a0 * v0b.x; acc0.w += a0 * v0b.y;
        }
    }
    float4 acc = make_float4(acc0.x + acc1.x, acc0.y + acc1.y,
                             acc0.z + acc1.z, acc0.w + acc1.w);

    int j = lane * 4;
    float4 b = *reinterpret_cast<const float4*>(bias + j);
    float4 r = make_float4(acc.x + b.x, acc.y + b.y, acc.z + b.z, acc.w + b.w);
    if (FIRST) {
        float4 gm = *reinterpret_cast<const float4*>(gamma + j);
        float4 bt = *reinterpret_cast<const float4*>(beta + j);
        float4 mn = *reinterpret_cast<const float4*>(mean + j);
        float4 vr = *reinterpret_cast<const float4*>(var + j);
        r.x = (r.x - mn.x) * rsqrtf(vr.x + BN_EPS) * gm.x + bt.x;
        r.y = (r.y - mn.y) * rsqrtf(vr.y + BN_EPS) * gm.y + bt.y;
        r.z = (r.z - mn.z) * rsqrtf(vr.z + BN_EPS) * gm.z + bt.z;
        r.w = (r.w - mn.w) * rsqrtf(vr.w + BN_EPS) * gm.w + bt.w;
        r.x = r.x > 0.f ? r.x : expm1f(r.x);
        r.y = r.y > 0.f ? r.y : expm1f(r.y);
        r.z = r.z > 0.f ? r.z : expm1f(r.z);
        r.w = r.w > 0.f ? r.w : expm1f(r.w);
        *reinterpret_cast<float4*>(g_x1 + (size_t)w * HC + j) = r;
    } else {
        float4 p1 = *reinterpret_cast<const float4*>(g_x1 + (size_t)w * HC + j);
        r.x = fmaxf(r.x, p1.x); r.y = fmaxf(r.y, p1.y);
        r.z = fmaxf(r.z, p1.z); r.w = fmaxf(r.w, p1.w);        // JK 'max'
        *reinterpret_cast<float4*>(g_x2 + (size_t)w * HC + j) = r;
    }
}

// ------- head GEMM (M=64/block, Nc=40, K=128) + fused bias + log-softmax -----
__global__ __launch_bounds__(256)
void k_head(const float* __restrict__ A, const float* __restrict__ B,
            const float* __restrict__ bf, float* __restrict__ out, int M) {
    __shared__ __align__(16) float As[16][64];
    __shared__ __align__(16) float Bs[16][64];
    __shared__ float sred[64][17];
    __shared__ float srow[64];
    int t  = threadIdx.x;
    int tx = t & 15, ty = t >> 4;
    int rowBase = blockIdx.x * 64;

    float acc[4][4] = {};
    int aRow = t >> 2;
    int aK4  = (t & 3) * 4;
    int bK   = t >> 4;
    int bC4  = (t & 15) * 4;

    for (int k0 = 0; k0 < 128; k0 += 16) {
        float4 av = make_float4(0.f, 0.f, 0.f, 0.f);
        int gr = rowBase + aRow;
        if (gr < M) av = *reinterpret_cast<const float4*>(A + (size_t)gr * 128 + k0 + aK4);
        As[aK4 + 0][aRow] = av.x; As[aK4 + 1][aRow] = av.y;
        As[aK4 + 2][aRow] = av.z; As[aK4 + 3][aRow] = av.w;

        float4 bv = make_float4(0.f, 0.f, 0.f, 0.f);
        const float* brow = B + (size_t)(k0 + bK) * NOUTC;
        if (bC4 + 0 < NOUTC) bv.x = brow[bC4 + 0];
        if (bC4 + 1 < NOUTC) bv.y = brow[bC4 + 1];
        if (bC4 + 2 < NOUTC) bv.z = brow[bC4 + 2];
        if (bC4 + 3 < NOUTC) bv.w = brow[bC4 + 3];
        *reinterpret_cast<float4*>(&Bs[bK][bC4]) = bv;
        __syncthreads();

        #pragma unroll
        for (int k = 0; k < 16; k++) {
            float4 a4 = *reinterpret_cast<const float4*>(&As[k][ty * 4]);
            float4 b4 = *reinterpret_cast<const float4*>(&Bs[k][tx * 4]);
            float a[4] = {a4.x, a4.y, a4.z, a4.w};
            float b[4] = {b4.x, b4.y, b4.z, b4.w};
            #pragma unroll
            for (int i = 0; i < 4; i++)
                #pragma unroll
                for (int j = 0; j < 4; j++)
                    acc[i][j] += a[i] * b[j];
        }
        __syncthreads();
    }

    // add bias -> logits (cols tx*4+j, valid < 40)
    float bfv[4];
    #pragma unroll
    for (int j = 0; j < 4; j++)
        bfv[j] = (tx * 4 + j < NOUTC) ? bf[tx * 4 + j] : 0.f;
    #pragma unroll
    for (int i = 0; i < 4; i++)
        #pragma unroll
        for (int j = 0; j < 4; j++)
            acc[i][j] += bfv[j];

    // row max partials
    #pragma unroll
    for (int i = 0; i < 4; i++) {
        float pm = -3.0e38f;
        #pragma unroll
        for (int j = 0; j < 4; j++)
            if (tx * 4 + j < NOUTC) pm = fmaxf(pm, acc[i][j]);
        sred[ty * 4 + i][tx] = pm;
    }
    __syncthreads();
    if (t < 64) {
        float m = -3.0e38f;
        #pragma unroll
        for (int k = 0; k < 10; k++) m = fmaxf(m, sred[t][k]);
        srow[t] = m;
    }
    __syncthreads();
    // row sum partials
    #pragma unroll
    for (int i = 0; i < 4; i++) {
        float m = srow[ty * 4 + i];
        float ps = 0.f;
        #pragma unroll
        for (int j = 0; j < 4; j++)
            if (tx * 4 + j < NOUTC) ps += expf(acc[i][j] - m);
        sred[ty * 4 + i][tx] = ps;
    }
    __syncthreads();
    if (t < 64) {
        float s = 0.f;
        #pragma unroll
        for (int k = 0; k < 10; k++) s += sred[t][k];
        srow[t] += logf(s);           // lse
    }
    __syncthreads();

    #pragma unroll
    for (int i = 0; i < 4; i++) {
        int gr = rowBase + ty * 4 + i;
        if (gr >= M) continue;
        float lse = srow[ty * 4 + i];
        #pragma unroll
        for (int j = 0; j < 4; j++) {
            int gc = tx * 4 + j;
            if (gc < NOUTC) out[(size_t)gr * NOUTC + gc] = acc[i][j] - lse;
        }
    }
}

// ---------------- launch (single stream) -------------------------------------
extern "C" void kernel_launch(void* const* d_in, const int* in_sizes, int n_in,
                              void* d_out, int out_size) {
    const float* x     = (const float*)d_in[0];
    const void*  ei    = d_in[1];
    const float* W1    = (const float*)d_in[2];
    const float* as1   = (const float*)d_in[3];
    const float* ad1   = (const float*)d_in[4];
    const float* b1    = (const float*)d_in[5];
    const float* gamma = (const float*)d_in[6];
    const float* beta  = (const float*)d_in[7];
    const float* mean  = (const float*)d_in[8];
    const float* var   = (const float*)d_in[9];
    const float* W2    = (const float*)d_in[10];
    const float* as2   = (const float*)d_in[11];
    const float* ad2   = (const float*)d_in[12];
    const float* b2    = (const float*)d_in[13];
    const float* Wf    = (const float*)d_in[14];
    const float* bf    = (const float*)d_in[15];
    float* out = (float*)d_out;

    __half* hhP;
    float *x1P, *x2P;
    cudaGetSymbolAddress((void**)&hhP, g_hh);
    cudaGetSymbolAddress((void**)&x1P, g_x1);
    cudaGetSymbolAddress((void**)&x2P, g_x2);

    const int WPN = (NNODES * 32 + 255) / 256;   // warp-per-node grids
    dim3 gemmG((NNODES + 127) / 128);

    k_init<<<(NNODES + 255) / 256, 256>>>((const int*)ei);
    k_count<<<(ETOT + 255) / 256, 256>>>(ei);
    k_scan1<<<NSCANB, 1024>>>();
    k_scan3<<<NSCANB, 1024>>>();
    k_fill<<<(ETOT + 255) / 256, 256>>>(ei);

    // layer 1
    k_sgemm128<<<gemmG, 256>>>(x, W1, hhP, NNODES, as1, ad1);
    k_gat<true><<<WPN, 256>>>(b1, gamma, beta, mean, var);

    // layer 2
    k_sgemm128<<<gemmG, 256>>>(x1P, W2, hhP, NNODES, as2, ad2);
    k_gat<false><<<WPN, 256>>>(b2, nullptr, nullptr, nullptr, nullptr);

    // head: GEMM + bias + log-softmax fused
    k_head<<<(NNODES + 63) / 64, 256>>>(x2P, Wf, bf, out, NNODES);
}

// round 17
// speedup vs baseline: 1.1470x; 1.0253x over previous
#include <cuda_runtime.h>
#include <cuda_fp16.h>
#include <math.h>

#define NNODES 50000
#define NEDGES 800000
#define ETOT   (NEDGES + NNODES)
#define HC     128
#define NOUTC  40
#define NEG_SLOPE 0.2f
#define BN_EPS 1e-5f
#define NSCANB ((NNODES + 1023) / 1024)
#define FULLM 0xffffffffu

// ---------------- scratch (static device arrays; no runtime alloc) ----------
static __device__ __align__(16) __half g_hh[NNODES * HC];   // h in fp16 (gather)
static __device__ __align__(16) float g_x1[NNODES * HC];
static __device__ __align__(16) float g_x2[NNODES * HC];
static __device__ float g_asrc[NNODES * 2];
static __device__ float g_adst[NNODES * 2];
static __device__ __align__(16) float g_e[ETOT * 2];   // ex per edge (CSR order)
static __device__ int   g_deg[NNODES];
static __device__ int   g_rowptr[NNODES + 1];
static __device__ int   g_bsum[NSCANB + 1];
static __device__ int   g_tick[ETOT];
static __device__ int   g_csr_src[ETOT];
static __device__ int   g_is64;

// ---------------- half2 <-> u32 bit casts ------------------------------------
__device__ __forceinline__ unsigned int h2_to_u32(__half2 h) {
    return *reinterpret_cast<unsigned int*>(&h);
}
__device__ __forceinline__ __half2 u32_to_h2(unsigned int u) {
    return *reinterpret_cast<__half2*>(&u);
}

// ---------------- init: zero degrees + edge dtype detect ---------------------
__global__ void k_init(const int* ei32) {
    int i = blockIdx.x * blockDim.x + threadIdx.x;
    if (i < NNODES) g_deg[i] = 0;
    if (i == 0) {
        int any = 0;
        #pragma unroll 1
        for (int k = 0; k < 256; k++) any |= ei32[2 * k + 1];
        g_is64 = (any == 0) ? 1 : 0;   // int64 ids < 50000 -> high words all 0
    }
}

__device__ __forceinline__ int edge_idx(const void* ei, int pos) {
    if (g_is64) return (int)((const long long*)ei)[pos];
    return ((const int*)ei)[pos];
}

// ---------------- CSR scan + fill --------------------------------------------
__global__ void k_scan1() {
    __shared__ int s[1024];
    int t = threadIdx.x;
    int idx = blockIdx.x * 1024 + t;
    int v = (idx < NNODES) ? g_deg[idx] : 0;
    s[t] = v;
    __syncthreads();
    #pragma unroll
    for (int o = 1; o < 1024; o <<= 1) {
        int add = (t >= o) ? s[t - o] : 0;
        __syncthreads();
        s[t] += add;
        __syncthreads();
    }
    if (idx < NNODES) g_rowptr[idx + 1] = s[t];
    if (t == 1023) g_bsum[blockIdx.x] = s[1023];
    if (idx == 0) g_rowptr[0] = 0;
}

// merged block-sum prefix + offset add (warp-parallel prefix per block)
__global__ void k_scan3() {
    __shared__ int pre;
    int b = blockIdx.x;
    if (threadIdx.x < 32) {
        int v = 0;
        if (threadIdx.x < b) v = g_bsum[threadIdx.x];
        if (threadIdx.x + 32 < b) v += g_bsum[threadIdx.x + 32];
        #pragma unroll
        for (int o = 16; o; o >>= 1) v += __shfl_xor_sync(FULLM, v, o);
        if (threadIdx.x == 0) pre = v;
    }
    __syncthreads();
    int idx = b * 1024 + threadIdx.x;
    if (idx < NNODES) g_rowptr[idx + 1] += pre;
}

__global__ void k_fill(const void* ei) {
    int i = blockIdx.x * blockDim.x + threadIdx.x;
    if (i >= ETOT) return;
    int s, d;
    if (i < NEDGES) { s = edge_idx(ei, i); d = edge_idx(ei, NEDGES + i); }
    else            { s = d = i - NEDGES; }
    g_csr_src[g_rowptr[d] + g_tick[i]] = s;   // atomic-free (ticket)
}

// ---------------- FAT kernel: layer-1 SGEMM ∪ edge count ---------------------
// blocks [0, gemmBlocks): packed-f32x2 SGEMM (K=Nc=128), fp16 C, fused attn dots
// blocks [gemmBlocks, ..): per-edge degree count (independent of GEMM)
__device__ __forceinline__ unsigned long long pack2(float a) {
    unsigned long long r;
    unsigned int u = __float_as_uint(a);
    asm("mov.b64 %0, {%1, %1};" : "=l"(r) : "r"(u));
    return r;
}
__device__ __forceinline__ float2 unpack2(unsigned long long v) {
    float2 f;
    asm("mov.b64 {%0, %1}, %2;" : "=f"(f.x), "=f"(f.y) : "l"(v));
    return f;
}

__device__ void gemm128_body(const float* __restrict__ A, const float* __restrict__ B,
                             __half* __restrict__ C, int M,
                             const float* __restrict__ att_src,
                             const float* __restrict__ att_dst,
                             int blockId, float* As_, float* Bs_) {
    float (*As)[128] = reinterpret_cast<float (*)[128]>(As_);
    float (*Bs)[128] = reinterpret_cast<float (*)[128]>(Bs_);
    int t  = threadIdx.x;
    int tx = t & 15, ty = t >> 4;
    int rowBase = blockId * 128;

    unsigned long long acc[8][4];
    #pragma unroll
    for (int i = 0; i < 8; i++)
        #pragma unroll
        for (int j = 0; j < 4; j++) acc[i][j] = 0ull;

    int aRow = t >> 1;          // 0..127
    int aK   = (t & 1) * 8;     // 0 or 8
    int bRow = t >> 4;          // 0..15
    int bC   = (t & 15) * 8;    // 0..120

    for (int k0 = 0; k0 < 128; k0 += 16) {
        float4 av0 = make_float4(0.f, 0.f, 0.f, 0.f), av1 = av0;
        int gr = rowBase + aRow;
        if (gr < M) {
            const float* ap = A + (size_t)gr * 128 + k0 + aK;
            av0 = *reinterpret_cast<const float4*>(ap);
            av1 = *reinterpret_cast<const float4*>(ap + 4);
        }
        As[aK + 0][aRow] = av0.x; As[aK + 1][aRow] = av0.y;
        As[aK + 2][aRow] = av0.z; As[aK + 3][aRow] = av0.w;
        As[aK + 4][aRow] = av1.x; As[aK + 5][aRow] = av1.y;
        As[aK + 6][aRow] = av1.z; As[aK + 7][aRow] = av1.w;

        const float* bp = B + (size_t)(k0 + bRow) * 128 + bC;
        *reinterpret_cast<float4*>(&Bs[bRow][bC])     = *reinterpret_cast<const float4*>(bp);
        *reinterpret_cast<float4*>(&Bs[bRow][bC + 4]) = *reinterpret_cast<const float4*>(bp + 4);
        __syncthreads();

        #pragma unroll
        for (int k = 0; k < 16; k++) {
            float4 a0 = *reinterpret_cast<const float4*>(&As[k][ty * 8]);
            float4 a1 = *reinterpret_cast<const float4*>(&As[k][ty * 8 + 4]);
            unsigned long long aa[8];
            aa[0] = pack2(a0.x); aa[1] = pack2(a0.y); aa[2] = pack2(a0.z); aa[3] = pack2(a0.w);
            aa[4] = pack2(a1.x); aa[5] = pack2(a1.y); aa[6] = pack2(a1.z); aa[7] = pack2(a1.w);
            const unsigned long long* bpp =
                reinterpret_cast<const unsigned long long*>(&Bs[k][tx * 8]);
            unsigned long long b0 = bpp[0], b1 = bpp[1], b2 = bpp[2], b3 = bpp[3];
            #pragma unroll
            for (int i = 0; i < 8; i++) {
                asm("fma.rn.f32x2 %0, %1, %2, %0;" : "+l"(acc[i][0]) : "l"(aa[i]), "l"(b0));
                asm("fma.rn.f32x2 %0, %1, %2, %0;" : "+l"(acc[i][1]) : "l"(aa[i]), "l"(b1));
                asm("fma.rn.f32x2 %0, %1, %2, %0;" : "+l"(acc[i][2]) : "l"(aa[i]), "l"(b2));
                asm("fma.rn.f32x2 %0, %1, %2, %0;" : "+l"(acc[i][3]) : "l"(aa[i]), "l"(b3));
            }
        }
        __syncthreads();
    }

    // store C as fp16 (8 cols = 4 half2 = 16 B per thread-row)
    #pragma unroll
    for (int i = 0; i < 8; i++) {
        int gr = rowBase + ty * 8 + i;
        if (gr >= M) continue;
        uint4 pk;
        float2 c0 = unpack2(acc[i][0]);
        float2 c1 = unpack2(acc[i][1]);
        float2 c2 = unpack2(acc[i][2]);
        float2 c3 = unpack2(acc[i][3]);
        pk.x = h2_to_u32(__float22half2_rn(c0));
        pk.y = h2_to_u32(__float22half2_rn(c1));
        pk.z = h2_to_u32(__float22half2_rn(c2));
        pk.w = h2_to_u32(__float22half2_rn(c3));
        *reinterpret_cast<uint4*>(C + (size_t)gr * 128 + tx * 8) = pk;
    }

    // fused attention dot-products (fp32 accumulators)
    float asv[8], adv[8];
    #pragma unroll
    for (int j = 0; j < 8; j++) {
        asv[j] = att_src[tx * 8 + j];
        adv[j] = att_dst[tx * 8 + j];
    }
    float* sredS = &As[0][0];   // [128][16]
    float* sredD = &Bs[0][0];
    #pragma unroll
    for (int i = 0; i < 8; i++) {
        float ps = 0.f, pd = 0.f;
        #pragma unroll
        for (int j = 0; j < 4; j++) {
            float2 c = unpack2(acc[i][j]);
            ps += c.x * asv[2 * j] + c.y * asv[2 * j + 1];
            pd += c.x * adv[2 * j] + c.y * adv[2 * j + 1];
        }
        int row = ty * 8 + i;
        sredS[row * 16 + tx] = ps;
        sredD[row * 16 + tx] = pd;
    }
    __syncthreads();
    {
        int row  = t >> 1;
        int half = t & 1;
        int gr = rowBase + row;
        if (gr < M) {
            float ss = 0.f, sd = 0.f;
            #pragma unroll
            for (int k = 0; k < 8; k++) {
                ss += sredS[row * 16 + half * 8 + k];
                sd += sredD[row * 16 + half * 8 + k];
            }
            g_asrc[gr * 2 + half] = ss;
            g_adst[gr * 2 + half] = sd;
        }
    }
}

__global__ __launch_bounds__(256, 2)
void k_gemm1_count(const float* __restrict__ A, const float* __restrict__ B,
                   __half* __restrict__ C, int M,
                   const float* __restrict__ att_src, const float* __restrict__ att_dst,
                   const void* __restrict__ ei, int gemmBlocks) {
    __shared__ __align__(16) float As[16][128];
    __shared__ __align__(16) float Bs[16][128];
    if ((int)blockIdx.x < gemmBlocks) {
        gemm128_body(A, B, C, M, att_src, att_dst, blockIdx.x, &As[0][0], &Bs[0][0]);
    } else {
        int i = (blockIdx.x - gemmBlocks) * blockDim.x + threadIdx.x;
        if (i < ETOT) {
            int d = (i < NEDGES) ? edge_idx(ei, NEDGES + i) : (i - NEDGES);
            g_tick[i] = atomicAdd(&g_deg[d], 1);
        }
    }
}

// plain layer-2 GEMM (no count)
__global__ __launch_bounds__(256, 2)
void k_sgemm128(const float* __restrict__ A, const float* __restrict__ B,
                __half* __restrict__ C, int M,
                const float* __restrict__ att_src, const float* __restrict__ att_dst) {
    __shared__ __align__(16) float As[16][128];
    __shared__ __align__(16) float Bs[16][128];
    gemm128_body(A, B, C, M, att_src, att_dst, blockIdx.x, &As[0][0], &Bs[0][0]);
}

// ------- fused softmax + aggregate: 2 passes, no max-shift, fast exp ---------
// softmax is shift-invariant; |e| <= ~10 here so exp(e) is safe in fp32.
template <bool FIRST>
__global__ __launch_bounds__(256)
void k_gat(const float* __restrict__ bias,
           const float* __restrict__ gamma, const float* __restrict__ beta,
           const float* __restrict__ mean,  const float* __restrict__ var) {
    int gt = blockIdx.x * blockDim.x + threadIdx.x;
    int w = gt >> 5, lane = gt & 31;
    if (w >= NNODES) return;
    int beg = g_rowptr[w], end = g_rowptr[w + 1];
    float ad0 = g_adst[w * 2], ad1 = g_adst[w * 2 + 1];

    // pass 1: ex = exp(leaky(e)), store; accumulate denominator (lane-strided)
    float s0 = 0.f, s1 = 0.f;
    for (int p = beg + lane; p < end; p += 32) {
        int s = g_csr_src[p];
        float2 av = *reinterpret_cast<const float2*>(g_asrc + 2 * s);
        float e0 = av.x + ad0;
        float e1 = av.y + ad1;
        e0 = e0 > 0.f ? e0 : NEG_SLOPE * e0;
        e1 = e1 > 0.f ? e1 : NEG_SLOPE * e1;
        float x0 = __expf(e0);
        float x1 = __expf(e1);
        float2 ev; ev.x = x0; ev.y = x1;
        *reinterpret_cast<float2*>(g_e + 2 * p) = ev;
        s0 += x0; s1 += x1;
    }
    #pragma unroll
    for (int o = 16; o; o >>= 1) {
        s0 += __shfl_xor_sync(FULLM, s0, o);
        s1 += __shfl_xor_sync(FULLM, s1, o);
    }
    float inv0 = 1.f / (s0 + 1e-16f);
    float inv1 = 1.f / (s1 + 1e-16f);
    float invh = (lane < 16) ? inv0 : inv1;
    __syncwarp();

    // pass 2: fp16 gather with broadcast ex * inv, dual accumulators for MLP
    float4 acc0 = make_float4(0.f, 0.f, 0.f, 0.f);
    float4 acc1 = make_float4(0.f, 0.f, 0.f, 0.f);
    int p = beg;
    for (; p + 1 < end; p += 2) {
        int s0i = g_csr_src[p];
        int s1i = g_csr_src[p + 1];
        float2 e0 = *reinterpret_cast<const float2*>(g_e + 2 * p);
        float2 e1 = *reinterpret_cast<const float2*>(g_e + 2 * (p + 1));
        float a0 = ((lane < 16) ? e0.x : e0.y) * invh;
        float a1 = ((lane < 16) ? e1.x : e1.y) * invh;
        uint2 u0 = *reinterpret_cast<const uint2*>(g_hh + (size_t)s0i * HC + lane * 4);
        uint2 u1 = *reinterpret_cast<const uint2*>(g_hh + (size_t)s1i * HC + lane * 4);
        float2 v0a = __half22float2(u32_to_h2(u0.x));
        float2 v0b = __half22float2(u32_to_h2(u0.y));
        float2 v1a = __half22float2(u32_to_h2(u1.x));
        float2 v1b = __half22float2(u32_to_h2(u1.y));
        acc0.x += a0 * v0a.x; acc0.y += a0 * v0a.y;
        acc0.z += a0 * v0b.x; acc0.w += a0 * v0b.y;
        acc1.x += a1 * v1a.x; acc1.y += a1 * v1a.y;
        acc1.z += a1 * v1b.x; acc1.w += a1 * v1b.y;
    }
    if (p < end) {
        int s0i = g_csr_src[p];
        float2 e0 = *reinterpret_cast<const float2*>(g_e + 2 * p);
        float a0 = ((lane < 16) ? e0.x : e0.y) * invh;
        uint2 u0 = *reinterpret_cast<const uint2*>(g_hh + (size_t)s0i * HC + lane * 4);
        float2 v0a = __half22float2(u32_to_h2(u0.x));
        float2 v0b = __half22float2(u32_to_h2(u0.y));
        acc0.x += a0 * v0a.x; acc0.y += a0 * v0a.y;
        acc0.z += a0 * v0b.x; acc0.w += a0 * v0b.y;
    }
    float4 acc = make_float4(acc0.x + acc1.x, acc0.y + acc1.y,
                             acc0.z + acc1.z, acc0.w + acc1.w);

    int j = lane * 4;
    float4 b = *reinterpret_cast<const float4*>(bias + j);
    float4 r = make_float4(acc.x + b.x, acc.y + b.y, acc.z + b.z, acc.w + b.w);
    if (FIRST) {
        float4 gm = *reinterpret_cast<const float4*>(gamma + j);
        float4 bt = *reinterpret_cast<const float4*>(beta + j);
        float4 mn = *reinterpret_cast<const float4*>(mean + j);
        float4 vr = *reinterpret_cast<const float4*>(var + j);
        r.x = (r.x - mn.x) * rsqrtf(vr.x + BN_EPS) * gm.x + bt.x;
        r.y = (r.y - mn.y) * rsqrtf(vr.y + BN_EPS) * gm.y + bt.y;
        r.z = (r.z - mn.z) * rsqrtf(vr.z + BN_EPS) * gm.z + bt.z;
        r.w = (r.w - mn.w) * rsqrtf(vr.w + BN_EPS) * gm.w + bt.w;
        r.x = r.x > 0.f ? r.x : expm1f(r.x);
        r.y = r.y > 0.f ? r.y : expm1f(r.y);
        r.z = r.z > 0.f ? r.z : expm1f(r.z);
        r.w = r.w > 0.f ? r.w : expm1f(r.w);
        *reinterpret_cast<float4*>(g_x1 + (size_t)w * HC + j) = r;
    } else {
        float4 p1 = *reinterpret_cast<const float4*>(g_x1 + (size_t)w * HC + j);
        r.x = fmaxf(r.x, p1.x); r.y = fmaxf(r.y, p1.y);
        r.z = fmaxf(r.z, p1.z); r.w = fmaxf(r.w, p1.w);        // JK 'max'
        *reinterpret_cast<float4*>(g_x2 + (size_t)w * HC + j) = r;
    }
}

// ------- head GEMM (M=64/block, Nc=40, K=128) + fused bias + log-softmax -----
__global__ __launch_bounds__(256)
void k_head(const float* __restrict__ A, const float* __restrict__ B,
            const float* __restrict__ bf, float* __restrict__ out, int M) {
    __shared__ __align__(16) float As[16][64];
    __shared__ __align__(16) float Bs[16][64];
    __shared__ float sred[64][17];
    __shared__ float srow[64];
    int t  = threadIdx.x;
    int tx = t & 15, ty = t >> 4;
    int rowBase = blockIdx.x * 64;

    float acc[4][4] = {};
    int aRow = t >> 2;
    int aK4  = (t & 3) * 4;
    int bK   = t >> 4;
    int bC4  = (t & 15) * 4;

    for (int k0 = 0; k0 < 128; k0 += 16) {
        float4 av = make_float4(0.f, 0.f, 0.f, 0.f);
        int gr = rowBase + aRow;
        if (gr < M) av = *reinterpret_cast<const float4*>(A + (size_t)gr * 128 + k0 + aK4);
        As[aK4 + 0][aRow] = av.x; As[aK4 + 1][aRow] = av.y;
        As[aK4 + 2][aRow] = av.z; As[aK4 + 3][aRow] = av.w;

        float4 bv = make_float4(0.f, 0.f, 0.f, 0.f);
        const float* brow = B + (size_t)(k0 + bK) * NOUTC;
        if (bC4 + 0 < NOUTC) bv.x = brow[bC4 + 0];
        if (bC4 + 1 < NOUTC) bv.y = brow[bC4 + 1];
        if (bC4 + 2 < NOUTC) bv.z = brow[bC4 + 2];
        if (bC4 + 3 < NOUTC) bv.w = brow[bC4 + 3];
        *reinterpret_cast<float4*>(&Bs[bK][bC4]) = bv;
        __syncthreads();

        #pragma unroll
        for (int k = 0; k < 16; k++) {
            float4 a4 = *reinterpret_cast<const float4*>(&As[k][ty * 4]);
            float4 b4 = *reinterpret_cast<const float4*>(&Bs[k][tx * 4]);
            float a[4] = {a4.x, a4.y, a4.z, a4.w};
            float b[4] = {b4.x, b4.y, b4.z, b4.w};
            #pragma unroll
            for (int i = 0; i < 4; i++)
                #pragma unroll
                for (int j = 0; j < 4; j++)
                    acc[i][j] += a[i] * b[j];
        }
        __syncthreads();
    }

    // add bias -> logits (cols tx*4+j, valid < 40)
    float bfv[4];
    #pragma unroll
    for (int j = 0; j < 4; j++)
        bfv[j] = (tx * 4 + j < NOUTC) ? bf[tx * 4 + j] : 0.f;
    #pragma unroll
    for (int i = 0; i < 4; i++)
        #pragma unroll
        for (int j = 0; j < 4; j++)
            acc[i][j] += bfv[j];

    // row max partials
    #pragma unroll
    for (int i = 0; i < 4; i++) {
        float pm = -3.0e38f;
        #pragma unroll
        for (int j = 0; j < 4; j++)
            if (tx * 4 + j < NOUTC) pm = fmaxf(pm, acc[i][j]);
        sred[ty * 4 + i][tx] = pm;
    }
    __syncthreads();
    if (t < 64) {
        float m = -3.0e38f;
        #pragma unroll
        for (int k = 0; k < 10; k++) m = fmaxf(m, sred[t][k]);
        srow[t] = m;
    }
    __syncthreads();
    // row sum partials
    #pragma unroll
    for (int i = 0; i < 4; i++) {
        float m = srow[ty * 4 + i];
        float ps = 0.f;
        #pragma unroll
        for (int j = 0; j < 4; j++)
            if (tx * 4 + j < NOUTC) ps += expf(acc[i][j] - m);
        sred[ty * 4 + i][tx] = ps;
    }
    __syncthreads();
    if (t < 64) {
        float s = 0.f;
        #pragma unroll
        for (int k = 0; k < 10; k++) s += sred[t][k];
        srow[t] += logf(s);           // lse
    }
    __syncthreads();

    #pragma unroll
    for (int i = 0; i < 4; i++) {
        int gr = rowBase + ty * 4 + i;
        if (gr >= M) continue;
        float lse = srow[ty * 4 + i];
        #pragma unroll
        for (int j = 0; j < 4; j++) {
            int gc = tx * 4 + j;
            if (gc < NOUTC) out[(size_t)gr * NOUTC + gc] = acc[i][j] - lse;
        }
    }
}

// ---------------- launch (single stream) -------------------------------------
extern "C" void kernel_launch(void* const* d_in, const int* in_sizes, int n_in,
                              void* d_out, int out_size) {
    const float* x     = (const float*)d_in[0];
    const void*  ei    = d_in[1];
    const float* W1    = (const float*)d_in[2];
    const float* as1   = (const float*)d_in[3];
    const float* ad1   = (const float*)d_in[4];
    const float* b1    = (const float*)d_in[5];
    const float* gamma = (const float*)d_in[6];
    const float* beta  = (const float*)d_in[7];
    const float* mean  = (const float*)d_in[8];
    const float* var   = (const float*)d_in[9];
    const float* W2    = (const float*)d_in[10];
    const float* as2   = (const float*)d_in[11];
    const float* ad2   = (const float*)d_in[12];
    const float* b2    = (const float*)d_in[13];
    const float* Wf    = (const float*)d_in[14];
    const float* bf    = (const float*)d_in[15];
    float* out = (float*)d_out;

    __half* hhP;
    float *x1P, *x2P;
    cudaGetSymbolAddress((void**)&hhP, g_hh);
    cudaGetSymbolAddress((void**)&x1P, g_x1);
    cudaGetSymbolAddress((void**)&x2P, g_x2);

    const int WPN = (NNODES * 32 + 255) / 256;   // warp-per-node grids
    const int gemmG = (NNODES + 127) / 128;      // 391
    const int cntG  = (ETOT + 255) / 256;        // 3321

    k_init<<<(NNODES + 255) / 256, 256>>>((const int*)ei);

    // FAT: layer-1 GEMM ∪ degree count (independent work, one launch)
    k_gemm1_count<<<gemmG + cntG, 256>>>(x, W1, hhP, NNODES, as1, ad1, ei, gemmG);

    k_scan1<<<NSCANB, 1024>>>();
    k_scan3<<<NSCANB, 1024>>>();
    k_fill<<<(ETOT + 255) / 256, 256>>>(ei);

    // layer 1 aggregate
    k_gat<true><<<WPN, 256>>>(b1, gamma, beta, mean, var);

    // layer 2
    k_sgemm128<<<gemmG, 256>>>(x1P, W2, hhP, NNODES, as2, ad2);
    k_gat<false><<<WPN, 256>>>(b2, nullptr, nullptr, nullptr, nullptr);

    // head: GEMM + bias + log-softmax fused
    k_head<<<(NNODES + 63) / 64, 256>>>(x2P, Wf, bf, out, NNODES);
}